// round 15
// baseline (speedup 1.0000x reference)
#include <cuda_runtime.h>
#include <cuda_fp16.h>
#include <math.h>

#define NNODES 250000
#define NEDGES 4000000
#define DIM 64
#define CAP 64            // padded adjacency capacity per row (max deg ~40)

// -------- scratch (device globals; allocation is forbidden) --------
__device__ int    g_cnt[NNODES];
__device__ __align__(16) int g_colpad[(size_t)NNODES * CAP];
// pre-scaled features s[r] = dis[r]*feat[r], fp16 packed: 8 float4 = 128 B/row
__device__ __align__(128) float4 g_sA[(size_t)NNODES * 8];
__device__ __align__(128) float4 g_sB[(size_t)NNODES * 8];

__global__ void k_zero() {
    int i = blockIdx.x * blockDim.x + threadIdx.x;
    if (i < NNODES) g_cnt[i] = 0;
}

// -------- one-pass padded-bucket adjacency build, 2 edges/thread --------
__global__ void k_fill(const int* __restrict__ edge) {
    int t = blockIdx.x * blockDim.x + threadIdx.x;
    int e = t * 2;
    if (e >= NEDGES) return;
    // two independent atomic+scatter chains in flight
    int r0 = __ldcs(&edge[e]);
    int r1 = __ldcs(&edge[e + 1]);
    int c0 = __ldcs(&edge[NEDGES + e]);
    int c1 = __ldcs(&edge[NEDGES + e + 1]);
    int s0 = atomicAdd(&g_cnt[r0], 1);
    int s1 = atomicAdd(&g_cnt[r1], 1);
    if (s0 < CAP) g_colpad[(size_t)r0 * CAP + s0] = c0;
    if (s1 < CAP) g_colpad[(size_t)r1 * CAP + s1] = c1;
}

// s0 = rsqrt(deg+1) * emb, packed fp16. One thread per 8-dim chunk.
__global__ void k_disscale(const float* __restrict__ emb) {
    int t = blockIdx.x * blockDim.x + threadIdx.x;
    if (t >= NNODES * 8) return;
    int r = t >> 3;
    int chunk = t & 7;
    float d = rsqrtf((float)(g_cnt[r] + 1));     // +1 self loop; > 0
    const float4* e4 = (const float4*)emb;       // 16 float4 per row
    float4 a = __ldcs(&e4[(size_t)r * 16 + chunk * 2]);
    float4 b = __ldcs(&e4[(size_t)r * 16 + chunk * 2 + 1]);
    float4 outv;
    __half2* h = (__half2*)&outv;
    h[0] = __floats2half2_rn(d * a.x, d * a.y);
    h[1] = __floats2half2_rn(d * a.z, d * a.w);
    h[2] = __floats2half2_rn(d * b.x, d * b.y);
    h[3] = __floats2half2_rn(d * b.z, d * b.w);
    g_sA[t] = outv;
}

// packed f32x2 accumulate of a half2-packed float4 into 4 x (f32,f32) accs
__device__ __forceinline__ void accp(unsigned long long* acc, float4 v) {
    __half2* h = (__half2*)&v;
    #pragma unroll
    for (int i = 0; i < 4; i++) {
        float2 f = __half22float2(h[i]);
        unsigned long long p;
        asm("mov.b64 %0, {%1, %2};" : "=l"(p) : "f"(f.x), "f"(f.y));
        asm("add.rn.f32x2 %0, %0, %1;" : "+l"(acc[i]) : "l"(p));
    }
}

// -------- SpMM: 8 lanes per row, 4 rows per warp, software-pipelined --------
// group g = lane>>3 owns row r = warp*4 + g; chunk = lane&7 owns dims
// [chunk*8, chunk*8+8). No cross-lane reduction; stores amortized across rows.
__global__ void __launch_bounds__(256) k_spmm(
                       const float4* __restrict__ sin,
                       float4* __restrict__ sout,             // nullable
                       float* __restrict__ o1, int s1,
                       float* __restrict__ o2, int s2) {      // o2 nullable
    int t = blockIdx.x * blockDim.x + threadIdx.x;
    int lane  = t & 31;
    int g     = lane >> 3;
    int chunk = lane & 7;
    int r = (t >> 5) * 4 + g;
    if (r >= NNODES) return;

    int cnt = __ldg(&g_cnt[r]);
    int deg = cnt > CAP ? CAP : cnt;
    float dr = rsqrtf((float)(cnt + 1));
    int beg = r * CAP;
    int end = beg + deg;

    unsigned long long acc[4];
    #pragma unroll
    for (int i = 0; i < 4; i++) acc[i] = 0ull;
    accp(acc, __ldg(&sin[(size_t)r * 8 + chunk]));   // self term (exact f32 acc)

    int e = beg;
    if (e + 2 <= end) {
        // prologue: load first pair
        int2 cc = __ldg((const int2*)&g_colpad[e]);
        float4 v0 = __ldg(&sin[(size_t)cc.x * 8 + chunk]);
        float4 v1 = __ldg(&sin[(size_t)cc.y * 8 + chunk]);
        e += 2;
        // pipelined: issue next pair's loads before consuming current
        for (; e + 2 <= end; e += 2) {
            int2 nc = __ldg((const int2*)&g_colpad[e]);
            float4 n0 = __ldg(&sin[(size_t)nc.x * 8 + chunk]);
            float4 n1 = __ldg(&sin[(size_t)nc.y * 8 + chunk]);
            float4 s;
            __half2* a = (__half2*)&v0;
            __half2* b = (__half2*)&v1;
            __half2* o = (__half2*)&s;
            #pragma unroll
            for (int i = 0; i < 4; i++) o[i] = __hadd2(a[i], b[i]);
            accp(acc, s);
            v0 = n0; v1 = n1;
        }
        // drain
        float4 s;
        __half2* a = (__half2*)&v0;
        __half2* b = (__half2*)&v1;
        __half2* o = (__half2*)&s;
        #pragma unroll
        for (int i = 0; i < 4; i++) o[i] = __hadd2(a[i], b[i]);
        accp(acc, s);
    }
    if (e < end) {
        int c = __ldg(&g_colpad[e]);
        accp(acc, __ldg(&sin[(size_t)c * 8 + chunk]));
    }

    // unpack packed accumulators
    float accf[8];
    #pragma unroll
    for (int i = 0; i < 4; i++) {
        float lo, hi;
        asm("mov.b64 {%0, %1}, %2;" : "=f"(lo), "=f"(hi) : "l"(acc[i]));
        accf[2 * i]     = lo;
        accf[2 * i + 1] = hi;
    }

    float4 oa = make_float4(dr * accf[0], dr * accf[1], dr * accf[2], dr * accf[3]);
    float4 ob = make_float4(dr * accf[4], dr * accf[5], dr * accf[6], dr * accf[7]);

    float4* dst1 = (float4*)(o1 + (size_t)r * s1 + chunk * 8);
    __stcs(dst1,     oa);
    __stcs(dst1 + 1, ob);
    if (o2) {
        float4* dst2 = (float4*)(o2 + (size_t)r * s2 + chunk * 8);
        __stcs(dst2,     oa);
        __stcs(dst2 + 1, ob);
    }
    if (sout) {
        float dr2 = dr * dr;
        float4 packed;
        __half2* h = (__half2*)&packed;
        h[0] = __floats2half2_rn(dr2 * accf[0], dr2 * accf[1]);
        h[1] = __floats2half2_rn(dr2 * accf[2], dr2 * accf[3]);
        h[2] = __floats2half2_rn(dr2 * accf[4], dr2 * accf[5]);
        h[3] = __floats2half2_rn(dr2 * accf[6], dr2 * accf[7]);
        sout[(size_t)r * 8 + chunk] = packed;    // next layer's gather source
    }
}

extern "C" void kernel_launch(void* const* d_in, const int* in_sizes, int n_in,
                              void* d_out, int out_size) {
    const int*   edge = (const int*)d_in[0];    // [2, NEDGES] int32
    const float* emb  = (const float*)d_in[1];  // [NNODES, 64] f32
    float* out = (float*)d_out;                 // [N*3*64] all_feat + [N*64] final

    float4 *sA, *sB;
    cudaGetSymbolAddress((void**)&sA, g_sA);
    cudaGetSymbolAddress((void**)&sB, g_sB);

    const int T = 256;
    // ---- adjacency build ----
    k_zero<<<(NNODES + T - 1) / T, T>>>();                    // 1
    k_fill<<<(NEDGES / 2 + T - 1) / T, T>>>(edge);            // 2
    k_disscale<<<(NNODES * 8 + T - 1) / T, T>>>(emb);         // 3

    // ---- 3 propagation layers ----
    // all_feat perm (2,0,1): out[:,0,:]=L3, out[:,1,:]=L1, out[:,2,:]=L2; final=L3
    int spmm_blocks = (NNODES * 8 + T - 1) / T;
    float* out_final = out + (size_t)NNODES * 3 * DIM;

    k_spmm<<<spmm_blocks, T>>>(sA, sB, out + DIM,     3 * DIM, nullptr,  0);     // 4: L1
    k_spmm<<<spmm_blocks, T>>>(sB, sA, out + 2 * DIM, 3 * DIM, nullptr,  0);     // 5: L2
    k_spmm<<<spmm_blocks, T>>>(sA, nullptr, out,      3 * DIM, out_final, DIM);  // 6: L3
}

// round 16
// speedup vs baseline: 1.3838x; 1.3838x over previous
#include <cuda_runtime.h>
#include <cuda_fp16.h>
#include <math.h>

#define NNODES 250000
#define NEDGES 4000000
#define DIM 64
#define CAP 64            // padded adjacency capacity per row (max deg ~40)

// -------- scratch (device globals; allocation is forbidden) --------
__device__ int    g_cnt[NNODES];
__device__ __align__(16) int g_colpad[(size_t)NNODES * CAP];
// pre-scaled features s[r] = dis[r]*feat[r], fp16 packed: 8 float4 = 128 B/row
__device__ __align__(128) float4 g_sA[(size_t)NNODES * 8];
__device__ __align__(128) float4 g_sB[(size_t)NNODES * 8];

__global__ void k_zero() {
    int i = blockIdx.x * blockDim.x + threadIdx.x;
    if (i < NNODES) g_cnt[i] = 0;
}

// -------- one-pass padded-bucket adjacency build --------
__global__ void k_fill(const int* __restrict__ edge) {
    int e = blockIdx.x * blockDim.x + threadIdx.x;
    if (e >= NEDGES) return;
    int r = __ldcs(&edge[e]);
    int c = __ldcs(&edge[NEDGES + e]);
    int slot = atomicAdd(&g_cnt[r], 1);
    if (slot < CAP) g_colpad[(size_t)r * CAP + slot] = c;
}

// s0 = rsqrt(deg+1) * emb, packed fp16. One thread per 8-dim chunk.
__global__ void k_disscale(const float* __restrict__ emb) {
    int t = blockIdx.x * blockDim.x + threadIdx.x;
    if (t >= NNODES * 8) return;
    int r = t >> 3;
    int chunk = t & 7;
    float d = rsqrtf((float)(g_cnt[r] + 1));     // +1 self loop; > 0
    const float4* e4 = (const float4*)emb;       // 16 float4 per row
    float4 a = __ldcs(&e4[(size_t)r * 16 + chunk * 2]);
    float4 b = __ldcs(&e4[(size_t)r * 16 + chunk * 2 + 1]);
    float4 outv;
    __half2* h = (__half2*)&outv;
    h[0] = __floats2half2_rn(d * a.x, d * a.y);
    h[1] = __floats2half2_rn(d * a.z, d * a.w);
    h[2] = __floats2half2_rn(d * b.x, d * b.y);
    h[3] = __floats2half2_rn(d * b.z, d * b.w);
    g_sA[t] = outv;
}

// packed f32x2 accumulate of a half2-packed float4 into 4 x (f32,f32) accs
__device__ __forceinline__ void accp(unsigned long long* acc, float4 v) {
    __half2* h = (__half2*)&v;
    #pragma unroll
    for (int i = 0; i < 4; i++) {
        float2 f = __half22float2(h[i]);
        unsigned long long p;
        asm("mov.b64 %0, {%1, %2};" : "=l"(p) : "f"(f.x), "f"(f.y));
        asm("add.rn.f32x2 %0, %0, %1;" : "+l"(acc[i]) : "l"(p));
    }
}

// -------- SpMM: 8 lanes per row, 4 rows per warp --------
// group g = lane>>3 owns row r = warp*4 + g; chunk = lane&7 owns dims
// [chunk*8, chunk*8+8). No cross-lane reduction; stores amortized across rows.
// min 7 blocks/SM (regs<=36) for 56 resident warps: latency-bound kernel.
__global__ void __launch_bounds__(256, 7) k_spmm(
                       const float4* __restrict__ sin,
                       float4* __restrict__ sout,             // nullable
                       float* __restrict__ o1, int s1,
                       float* __restrict__ o2, int s2) {      // o2 nullable
    int t = blockIdx.x * blockDim.x + threadIdx.x;
    int lane  = t & 31;
    int g     = lane >> 3;
    int chunk = lane & 7;
    int r = (t >> 5) * 4 + g;
    if (r >= NNODES) return;

    int cnt = __ldg(&g_cnt[r]);
    int deg = cnt > CAP ? CAP : cnt;
    float dr = rsqrtf((float)(cnt + 1));
    int beg = r * CAP;
    int end = beg + deg;

    unsigned long long acc[4];
    #pragma unroll
    for (int i = 0; i < 4; i++) acc[i] = 0ull;
    accp(acc, __ldg(&sin[(size_t)r * 8 + chunk]));   // self term (exact f32 acc)

    int e = beg;
    // 2 edges per iter: int2 col load (8B-aligned: beg is 64-aligned), fp16
    // pair-add then packed f32x2 accumulate.
    for (; e + 2 <= end; e += 2) {
        int2 cc = __ldg((const int2*)&g_colpad[e]);
        float4 v0 = __ldg(&sin[(size_t)cc.x * 8 + chunk]);
        float4 v1 = __ldg(&sin[(size_t)cc.y * 8 + chunk]);
        float4 s;
        __half2* a = (__half2*)&v0;
        __half2* b = (__half2*)&v1;
        __half2* o = (__half2*)&s;
        #pragma unroll
        for (int i = 0; i < 4; i++) o[i] = __hadd2(a[i], b[i]);
        accp(acc, s);
    }
    if (e < end) {
        int c = __ldg(&g_colpad[e]);
        accp(acc, __ldg(&sin[(size_t)c * 8 + chunk]));
    }

    // unpack packed accumulators
    float accf[8];
    #pragma unroll
    for (int i = 0; i < 4; i++) {
        float lo, hi;
        asm("mov.b64 {%0, %1}, %2;" : "=f"(lo), "=f"(hi) : "l"(acc[i]));
        accf[2 * i]     = lo;
        accf[2 * i + 1] = hi;
    }

    float4 oa = make_float4(dr * accf[0], dr * accf[1], dr * accf[2], dr * accf[3]);
    float4 ob = make_float4(dr * accf[4], dr * accf[5], dr * accf[6], dr * accf[7]);

    // every lane stores its own 8 dims; one STG covers 4 rows per warp
    float4* dst1 = (float4*)(o1 + (size_t)r * s1 + chunk * 8);
    __stcs(dst1,     oa);
    __stcs(dst1 + 1, ob);
    if (o2) {
        float4* dst2 = (float4*)(o2 + (size_t)r * s2 + chunk * 8);
        __stcs(dst2,     oa);
        __stcs(dst2 + 1, ob);
    }
    if (sout) {
        float dr2 = dr * dr;
        float4 packed;
        __half2* h = (__half2*)&packed;
        h[0] = __floats2half2_rn(dr2 * accf[0], dr2 * accf[1]);
        h[1] = __floats2half2_rn(dr2 * accf[2], dr2 * accf[3]);
        h[2] = __floats2half2_rn(dr2 * accf[4], dr2 * accf[5]);
        h[3] = __floats2half2_rn(dr2 * accf[6], dr2 * accf[7]);
        sout[(size_t)r * 8 + chunk] = packed;    // next layer's gather source
    }
}

extern "C" void kernel_launch(void* const* d_in, const int* in_sizes, int n_in,
                              void* d_out, int out_size) {
    const int*   edge = (const int*)d_in[0];    // [2, NEDGES] int32
    const float* emb  = (const float*)d_in[1];  // [NNODES, 64] f32
    float* out = (float*)d_out;                 // [N*3*64] all_feat + [N*64] final

    float4 *sA, *sB;
    cudaGetSymbolAddress((void**)&sA, g_sA);
    cudaGetSymbolAddress((void**)&sB, g_sB);

    const int T = 256;
    // ---- adjacency build ----
    k_zero<<<(NNODES + T - 1) / T, T>>>();                // 1
    k_fill<<<(NEDGES + T - 1) / T, T>>>(edge);            // 2
    k_disscale<<<(NNODES * 8 + T - 1) / T, T>>>(emb);     // 3

    // ---- 3 propagation layers ----
    // all_feat perm (2,0,1): out[:,0,:]=L3, out[:,1,:]=L1, out[:,2,:]=L2; final=L3
    // 8 threads per row -> N*8 threads per SpMM
    int spmm_blocks = (NNODES * 8 + T - 1) / T;
    float* out_final = out + (size_t)NNODES * 3 * DIM;

    k_spmm<<<spmm_blocks, T>>>(sA, sB, out + DIM,     3 * DIM, nullptr,  0);     // 4: L1
    k_spmm<<<spmm_blocks, T>>>(sB, sA, out + 2 * DIM, 3 * DIM, nullptr,  0);     // 5: L2
    k_spmm<<<spmm_blocks, T>>>(sA, nullptr, out,      3 * DIM, out_final, DIM);  // 6: L3
}